// round 16
// baseline (speedup 1.0000x reference)
#include <cuda_runtime.h>
#include <cuda_bf16.h>
#include <cuda_fp16.h>
#include <cstdint>

#define NB 8
#define PP 256
#define CC 128
#define US 132          // fp32 smem pad stride (proj kernel)

// ---- scratch (no allocation allowed) --------------------------------------
__device__ __align__(16) float g_M[CC*CC];     // Wp2 @ W1
__device__ __align__(16) float g_Wq1[CC*CC];   // Wq @ W1
__device__ __align__(16) float g_Wk1[CC*CC];   // Wk @ W1
__device__ __align__(16) float g_c0[CC];       // b1 + bp2 @ W1
__device__ __align__(16) float g_v[NB*PP*CC];
__device__ __align__(16) float g_qW1[NB*PP*CC];
__device__ __align__(16) float g_kW1[NB*PP*CC];
// Mt (=M^T) in fp16, n-major rows: row d (out dim), 128 k cols, packed half2
__device__ __align__(16) unsigned g_Bf[CC*64];

// ---- helpers --------------------------------------------------------------
__device__ __forceinline__ uint32_t smem_u32(const void* p) {
    uint32_t r;
    asm("{ .reg .u64 t; cvta.to.shared.u64 t, %1; cvt.u32.u64 %0, t; }" : "=r"(r) : "l"(p));
    return r;
}
__device__ __forceinline__ void ldsm_x4(uint32_t* r, uint32_t addr) {
    asm volatile("ldmatrix.sync.aligned.m8n8.x4.shared.b16 {%0,%1,%2,%3}, [%4];"
                 : "=r"(r[0]), "=r"(r[1]), "=r"(r[2]), "=r"(r[3]) : "r"(addr));
}
__device__ __forceinline__ void mma16816h(float* d, const uint32_t* a, uint32_t b0, uint32_t b1) {
    asm volatile("mma.sync.aligned.m16n8k16.row.col.f32.f16.f16.f32 "
                 "{%0,%1,%2,%3}, {%4,%5,%6,%7}, {%8,%9}, {%0,%1,%2,%3};"
                 : "+f"(d[0]), "+f"(d[1]), "+f"(d[2]), "+f"(d[3])
                 : "r"(a[0]), "r"(a[1]), "r"(a[2]), "r"(a[3]), "r"(b0), "r"(b1));
}
__device__ __forceinline__ unsigned pack_f16(float x, float y) {
    __half2 h = __floats2half2_rn(x, y);
    return *(unsigned*)&h;
}

// ---------------------------------------------------------------------------
// prep1: parallel weight-fold GEMMs (M, Wq1, Wk1, c0). grid (8,3), W1 in smem.
// ---------------------------------------------------------------------------
__global__ __launch_bounds__(256)
void prep1(const float* __restrict__ Wq, const float* __restrict__ Wk,
           const float* __restrict__ Wp2, const float* __restrict__ W1,
           const float* __restrict__ b1, const float* __restrict__ bp2) {
    extern __shared__ float sm[];
    float* W1s = sm;           // 16384 floats
    float* Ash = sm + CC*CC;   // 16*128
    const float* A = (blockIdx.y == 0) ? Wp2 : ((blockIdx.y == 1) ? Wq : Wk);
    float* O       = (blockIdx.y == 0) ? g_M : ((blockIdx.y == 1) ? g_Wq1 : g_Wk1);
    int r0 = blockIdx.x * 16;
    int tid = threadIdx.x;
    for (int i = tid; i < CC*CC/4; i += 256) ((float4*)W1s)[i] = ((const float4*)W1)[i];
    for (int i = tid; i < 16*CC/4; i += 256) ((float4*)Ash)[i] = ((const float4*)(A + r0*CC))[i];
    __syncthreads();
    int d = tid & 127, r2 = tid >> 7;
    #pragma unroll
    for (int rr = 0; rr < 8; rr++) {
        int r = r2*8 + rr;
        float s = 0.f;
        #pragma unroll 8
        for (int e = 0; e < CC; e++) s = fmaf(Ash[r*CC + e], W1s[e*CC + d], s);
        O[(r0 + r)*CC + d] = s;
    }
    if (blockIdx.x == 0 && blockIdx.y == 0 && tid < CC) {
        float s = b1[tid];
        for (int e = 0; e < CC; e++) s = fmaf(bp2[e], W1s[e*CC + tid], s);
        g_c0[tid] = s;
    }
}

// ---------------------------------------------------------------------------
// prep2: build Mt (=M^T) fp16, plain n-major (row=d, 64 packed k-pairs)
// ---------------------------------------------------------------------------
__global__ void prep2() {
    int i = blockIdx.x * 256 + threadIdx.x;      // 0..8191
    int d = i >> 6, pc = i & 63, c = pc * 2;
    g_Bf[d*64 + pc] = pack_f16(g_M[c*CC + d], g_M[(c+1)*CC + d]);
}

// ---------------------------------------------------------------------------
// proj: v = x@Wv, qW1 = x@Wq1, kW1 = x@Wk1  (fp32 SIMT)
// ---------------------------------------------------------------------------
__global__ __launch_bounds__(256, 2)
void proj_kernel(const float* __restrict__ x, const float* __restrict__ Wv) {
    extern __shared__ float sm[];
    float* Wsh = sm;
    float* Xsh = sm + CC*CC;
    int which = blockIdx.y;
    const float* W = (which == 0) ? Wv  : ((which == 1) ? g_Wq1 : g_Wk1);
    float*       O = (which == 0) ? g_v : ((which == 1) ? g_qW1 : g_kW1);
    int row0 = blockIdx.x * 64;
    int tid = threadIdx.x;
    for (int i = tid; i < CC*CC/4; i += 256) ((float4*)Wsh)[i] = ((const float4*)W)[i];
    for (int i = tid; i < 64*CC; i += 256) {
        int r = i >> 7, c = i & 127;
        Xsh[r*US + c] = x[(row0 + r)*CC + c];
    }
    __syncthreads();
    int tx = tid & 15, ty = tid >> 4;
    float acc[4][8];
    #pragma unroll
    for (int i = 0; i < 4; i++)
        #pragma unroll
        for (int j = 0; j < 8; j++) acc[i][j] = 0.f;
    #pragma unroll 4
    for (int c = 0; c < CC; c++) {
        float4 m0 = *(const float4*)&Wsh[c*CC + (tx << 3)];
        float4 m1 = *(const float4*)&Wsh[c*CC + (tx << 3) + 4];
        float m[8] = {m0.x, m0.y, m0.z, m0.w, m1.x, m1.y, m1.z, m1.w};
        float u[4];
        #pragma unroll
        for (int i = 0; i < 4; i++) u[i] = Xsh[(ty*4 + i)*US + c];
        #pragma unroll
        for (int i = 0; i < 4; i++)
            #pragma unroll
            for (int j = 0; j < 8; j++) acc[i][j] += u[i] * m[j];
    }
    #pragma unroll
    for (int i = 0; i < 4; i++) {
        float4* o4 = (float4*)&O[(row0 + ty*4 + i)*CC + (tx << 3)];
        o4[0] = make_float4(acc[i][0], acc[i][1], acc[i][2], acc[i][3]);
        o4[1] = make_float4(acc[i][4], acc[i][5], acc[i][6], acc[i][7]);
    }
}

// ---------------------------------------------------------------------------
// main: per (n,a) block, 256 threads / 8 warps, FOUR blocks/SM.
// A fragments synthesized IN REGISTERS from pos row constants + packed
// (wpa,wpb,bp) smem — no U smem, no A ldsm, no U-build phase. B from
// XOR-swizzled Bf (32KB). Gs fp16 buffer for coalesced epilogue. Shuffle
// softmax, att@v, residual.
// ---------------------------------------------------------------------------
__global__ __launch_bounds__(256, 4)
void main_kernel(const float* __restrict__ x, const float* __restrict__ pos,
                 const float* __restrict__ W2, const float* __restrict__ Wp1,
                 const float* __restrict__ bp1, float* __restrict__ out) {
    extern __shared__ __align__(16) char dyn[];
    __shared__ float kcsh[CC], W2sh[CC];
    __shared__ __align__(16) float4 wpk[CC];    // (wpa, wpb, bp, 0) per col
    __shared__ float logits[PP], red[PP], wred[16];

    const int blk = blockIdx.x;
    const int n = blk >> 8, a = blk & 255;
    const int tid = threadIdx.x;
    const int lane = tid & 31, w = tid >> 5;

    // dyn layout (bytes): Bf 32768 (swizzled, 256B rows) | Gs 17408 (pad 68)
    unsigned* Gs = (unsigned*)(dyn + 32768);
    const uint32_t BfA = smem_u32(dyn);

    // stage small vectors + B tile (swizzled granules: g' = g ^ (row&7))
    if (tid < CC) {
        kcsh[tid] = g_c0[tid] - g_kW1[(n*PP + a)*CC + tid];
        W2sh[tid] = W2[tid];
        wpk[tid] = make_float4(Wp1[tid], Wp1[CC + tid], bp1[tid], 0.f);
    }
    for (int i = tid; i < CC*16; i += 256) {
        int r = i >> 4, g = i & 15;
        uint4 v = ((const uint4*)(g_Bf + r*64))[g];
        *(uint4*)(dyn + r*256 + ((g ^ (r & 7)) << 4)) = v;
    }
    __syncthreads();

    // warp roles (GEMM)
    const int ci = w & 3;          // c-quarter: cols [ci*32, +32)
    const int mh = w >> 2;         // m-half within 64-row chunk
    const int n0 = ci * 32;
    const int m0 = mh * 32;

    const int brow = lane & 15;
    const int gb   = lane >> 4;                 // B granule base
    const uint32_t browb = (uint32_t)((n0 + brow) * 256);
    const int      brx   = brow & 7;
    const int kq = (lane & 3) * 2;              // A fragment k-col base (per quad)

    // hoisted per-lane epilogue constants: cols lane*4 .. lane*4+3
    const float kcE0 = kcsh[lane*4],   kcE1 = kcsh[lane*4+1];
    const float kcE2 = kcsh[lane*4+2], kcE3 = kcsh[lane*4+3];
    const float w2E0 = W2sh[lane*4],   w2E1 = W2sh[lane*4+1];
    const float w2E2 = W2sh[lane*4+2], w2E3 = W2sh[lane*4+3];

    const float2* posrow = (const float2*)(pos + (size_t)((n*PP + a)*PP) * 2);
    const float* qbase = g_qW1 + (size_t)(n*PP)*CC;

    #pragma unroll 1
    for (int chunk = 0; chunk < 4; chunk++) {
        // per-thread row constants for this chunk: rows m0 + (lane>>2) + 8j
        float2 p0 = __ldg(posrow + chunk*64 + m0 + (lane >> 2));
        float2 p1 = __ldg(posrow + chunk*64 + m0 + (lane >> 2) + 8);
        float2 p2 = __ldg(posrow + chunk*64 + m0 + (lane >> 2) + 16);
        float2 p3 = __ldg(posrow + chunk*64 + m0 + (lane >> 2) + 24);

        // warp GEMM: m32 x n32 x k128; A synthesized in registers
        float acc[2][4][4];
        #pragma unroll
        for (int ms = 0; ms < 2; ms++)
            #pragma unroll
            for (int nt = 0; nt < 4; nt++)
                #pragma unroll
                for (int e = 0; e < 4; e++) acc[ms][nt][e] = 0.f;

        #pragma unroll
        for (int kt = 0; kt < 8; kt++) {
            const uint32_t sw = (uint32_t)(((gb + 2*kt) ^ brx) << 4);
            uint32_t b0[4], b1[4];
            ldsm_x4(b0, BfA + browb + sw);
            ldsm_x4(b1, BfA + browb + 4096u + sw);

            // fragment k-cols for this kt
            const int c0 = kt*16 + kq;
            float4 wc0 = wpk[c0],     wc1 = wpk[c0 + 1];
            float4 wc8 = wpk[c0 + 8], wc9 = wpk[c0 + 9];

            #pragma unroll
            for (int ms = 0; ms < 2; ms++) {
                const float2 pa = (ms == 0) ? p0 : p2;
                const float2 pb = (ms == 0) ? p1 : p3;
                uint32_t ah[4];
                ah[0] = pack_f16(
                    fmaxf(fmaf(pa.x, wc0.x, fmaf(pa.y, wc0.y, wc0.z)), 0.f),
                    fmaxf(fmaf(pa.x, wc1.x, fmaf(pa.y, wc1.y, wc1.z)), 0.f));
                ah[1] = pack_f16(
                    fmaxf(fmaf(pb.x, wc0.x, fmaf(pb.y, wc0.y, wc0.z)), 0.f),
                    fmaxf(fmaf(pb.x, wc1.x, fmaf(pb.y, wc1.y, wc1.z)), 0.f));
                ah[2] = pack_f16(
                    fmaxf(fmaf(pa.x, wc8.x, fmaf(pa.y, wc8.y, wc8.z)), 0.f),
                    fmaxf(fmaf(pa.x, wc9.x, fmaf(pa.y, wc9.y, wc9.z)), 0.f));
                ah[3] = pack_f16(
                    fmaxf(fmaf(pb.x, wc8.x, fmaf(pb.y, wc8.y, wc8.z)), 0.f),
                    fmaxf(fmaf(pb.x, wc9.x, fmaf(pb.y, wc9.y, wc9.z)), 0.f));
                #pragma unroll
                for (int sub = 0; sub < 2; sub++) {
                    mma16816h(acc[ms][sub],   ah, b0[sub], b0[2+sub]);
                    mma16816h(acc[ms][2+sub], ah, b1[sub], b1[2+sub]);
                }
            }
        }

        // dump G (fp16 pairs) into Gs; conflict-free STS
        #pragma unroll
        for (int ms = 0; ms < 2; ms++)
            #pragma unroll
            for (int rh = 0; rh < 2; rh++) {
                int row = m0 + ms*16 + rh*8 + (lane >> 2);
                #pragma unroll
                for (int nt = 0; nt < 4; nt++) {
                    unsigned gp = pack_f16(acc[ms][nt][rh*2 + 0], acc[ms][nt][rh*2 + 1]);
                    Gs[row*68 + ci*16 + nt*4 + (lane & 3)] = gp;
                }
            }
        __syncthreads();

        // coalesced epilogue: warp w sweeps rows w*8..w*8+7; lane = 4 cols
        #pragma unroll 4
        for (int rr = 0; rr < 8; rr++) {
            int r = w*8 + rr;
            int bg = chunk*64 + r;
            uint2 g2 = *(const uint2*)&Gs[r*68 + lane*2];
            float4 q4 = __ldg((const float4*)(qbase + (size_t)bg*CC + lane*4));
            float2 ga = __half22float2(*(const __half2*)&g2.x);
            float2 gbv = __half22float2(*(const __half2*)&g2.y);
            float rp = fmaxf(ga.x  + q4.x + kcE0, 0.f) * w2E0;
            rp = fmaf(fmaxf(ga.y  + q4.y + kcE1, 0.f), w2E1, rp);
            rp = fmaf(fmaxf(gbv.x + q4.z + kcE2, 0.f), w2E2, rp);
            rp = fmaf(fmaxf(gbv.y + q4.w + kcE3, 0.f), w2E3, rp);
            #pragma unroll
            for (int o = 16; o > 0; o >>= 1) rp += __shfl_xor_sync(0xffffffffu, rp, o);
            if (lane == 0) logits[bg] = rp;
        }
        __syncthreads();   // Gs consumed before next chunk's dump
    }

    // softmax over b (256 entries) — shuffle-based
    float lv = logits[tid];
    {
        float m = lv;
        #pragma unroll
        for (int o = 16; o > 0; o >>= 1) m = fmaxf(m, __shfl_xor_sync(0xffffffffu, m, o));
        if (lane == 0) wred[w] = m;
    }
    __syncthreads();
    float mx = wred[0];
    #pragma unroll
    for (int i = 1; i < 8; i++) mx = fmaxf(mx, wred[i]);
    float ev = expf(lv - mx);
    {
        float s = ev;
        #pragma unroll
        for (int o = 16; o > 0; o >>= 1) s += __shfl_xor_sync(0xffffffffu, s, o);
        if (lane == 0) wred[8 + w] = s;
    }
    __syncthreads();
    float sum = (wred[8] + wred[9]) + (wred[10] + wred[11])
              + (wred[12] + wred[13]) + (wred[14] + wred[15]);
    logits[tid] = ev * (1.0f / sum);
    __syncthreads();

    // out[n,a,:] = x[n,a,:] + att @ v[n]   (2-way split of the b-sum)
    {
        int d = tid & 127, h = tid >> 7;       // h in 0..1
        const float* vb = &g_v[(size_t)(n*PP + h*128)*CC + d];
        float s0 = 0.f, s1 = 0.f;
        #pragma unroll 4
        for (int b = 0; b < 128; b += 2) {
            s0 = fmaf(logits[h*128 + b    ], vb[(size_t)b*CC],     s0);
            s1 = fmaf(logits[h*128 + b + 1], vb[(size_t)(b+1)*CC], s1);
        }
        red[tid] = s0 + s1;
    }
    __syncthreads();
    if (tid < CC) {
        size_t o = (size_t)(n*PP + a)*CC + tid;
        out[o] = x[o] + red[tid] + red[tid + 128];
    }
}

// ---------------------------------------------------------------------------
extern "C" void kernel_launch(void* const* d_in, const int* in_sizes, int n_in,
                              void* d_out, int out_size) {
    const float* x   = (const float*)d_in[0];
    const float* pos = (const float*)d_in[1];
    const float* Wq  = (const float*)d_in[2];
    const float* Wk  = (const float*)d_in[3];
    const float* Wv  = (const float*)d_in[4];
    const float* W1  = (const float*)d_in[5];
    const float* b1  = (const float*)d_in[6];
    const float* W2  = (const float*)d_in[7];
    // d_in[8] = b2: cancelled by softmax
    const float* Wp1 = (const float*)d_in[9];
    const float* bp1 = (const float*)d_in[10];
    const float* Wp2 = (const float*)d_in[11];
    const float* bp2 = (const float*)d_in[12];
    float* out = (float*)d_out;

    const int smem_prep = (CC*CC + 16*CC) * 4;   // 73728
    const int smem_proj = (CC*CC + 64*US) * 4;   // 99328
    const int smem_main = 50176;                 // Bf swizzled 32K + Gs 17K
    cudaFuncSetAttribute(prep1,       cudaFuncAttributeMaxDynamicSharedMemorySize, smem_prep);
    cudaFuncSetAttribute(proj_kernel, cudaFuncAttributeMaxDynamicSharedMemorySize, smem_proj);
    cudaFuncSetAttribute(main_kernel, cudaFuncAttributeMaxDynamicSharedMemorySize, smem_main);

    prep1<<<dim3(8, 3), 256, smem_prep>>>(Wq, Wk, Wp2, W1, b1, bp2);
    prep2<<<32, 256>>>();
    proj_kernel<<<dim3(NB*PP/64, 3), 256, smem_proj>>>(x, Wv);
    main_kernel<<<NB*PP, 256, smem_main>>>(x, pos, W2, Wp1, bp1, out);
}

// round 17
// speedup vs baseline: 1.4483x; 1.4483x over previous
#include <cuda_runtime.h>
#include <cuda_bf16.h>
#include <cuda_fp16.h>
#include <cstdint>

#define NB 8
#define PP 256
#define CC 128
#define US 132          // fp32 smem pad stride (proj kernel)
#define HS 136          // f16 smem pad stride in halves (Uf ldmatrix, conflict-free)

// ---- scratch (no allocation allowed) --------------------------------------
__device__ __align__(16) float g_M[CC*CC];     // Wp2 @ W1
__device__ __align__(16) float g_Wq1[CC*CC];   // Wq @ W1
__device__ __align__(16) float g_Wk1[CC*CC];   // Wk @ W1
__device__ __align__(16) float g_c0[CC];       // b1 + bp2 @ W1
__device__ __align__(16) float g_v[NB*PP*CC];
__device__ __align__(16) float g_qW1[NB*PP*CC];
__device__ __align__(16) float g_kW1[NB*PP*CC];
// Mt (=M^T) in fp16, n-major rows: row d (out dim), 128 k cols, packed half2
__device__ __align__(16) unsigned g_Bf[CC*64];

// ---- helpers --------------------------------------------------------------
__device__ __forceinline__ uint32_t smem_u32(const void* p) {
    uint32_t r;
    asm("{ .reg .u64 t; cvta.to.shared.u64 t, %1; cvt.u32.u64 %0, t; }" : "=r"(r) : "l"(p));
    return r;
}
__device__ __forceinline__ void ldsm_x4(uint32_t* r, uint32_t addr) {
    asm volatile("ldmatrix.sync.aligned.m8n8.x4.shared.b16 {%0,%1,%2,%3}, [%4];"
                 : "=r"(r[0]), "=r"(r[1]), "=r"(r[2]), "=r"(r[3]) : "r"(addr));
}
__device__ __forceinline__ void mma16816h(float* d, const uint32_t* a, uint32_t b0, uint32_t b1) {
    asm volatile("mma.sync.aligned.m16n8k16.row.col.f32.f16.f16.f32 "
                 "{%0,%1,%2,%3}, {%4,%5,%6,%7}, {%8,%9}, {%0,%1,%2,%3};"
                 : "+f"(d[0]), "+f"(d[1]), "+f"(d[2]), "+f"(d[3])
                 : "r"(a[0]), "r"(a[1]), "r"(a[2]), "r"(a[3]), "r"(b0), "r"(b1));
}
__device__ __forceinline__ unsigned pack_f16(float x, float y) {
    __half2 h = __floats2half2_rn(x, y);
    return *(unsigned*)&h;
}

// ---------------------------------------------------------------------------
// prep1: parallel weight-fold GEMMs (M, Wq1, Wk1, c0). grid (8,3), W1 in smem.
// ---------------------------------------------------------------------------
__global__ __launch_bounds__(256)
void prep1(const float* __restrict__ Wq, const float* __restrict__ Wk,
           const float* __restrict__ Wp2, const float* __restrict__ W1,
           const float* __restrict__ b1, const float* __restrict__ bp2) {
    extern __shared__ float sm[];
    float* W1s = sm;           // 16384 floats
    float* Ash = sm + CC*CC;   // 16*128
    const float* A = (blockIdx.y == 0) ? Wp2 : ((blockIdx.y == 1) ? Wq : Wk);
    float* O       = (blockIdx.y == 0) ? g_M : ((blockIdx.y == 1) ? g_Wq1 : g_Wk1);
    int r0 = blockIdx.x * 16;
    int tid = threadIdx.x;
    for (int i = tid; i < CC*CC/4; i += 256) ((float4*)W1s)[i] = ((const float4*)W1)[i];
    for (int i = tid; i < 16*CC/4; i += 256) ((float4*)Ash)[i] = ((const float4*)(A + r0*CC))[i];
    __syncthreads();
    int d = tid & 127, r2 = tid >> 7;
    #pragma unroll
    for (int rr = 0; rr < 8; rr++) {
        int r = r2*8 + rr;
        float s = 0.f;
        #pragma unroll 8
        for (int e = 0; e < CC; e++) s = fmaf(Ash[r*CC + e], W1s[e*CC + d], s);
        O[(r0 + r)*CC + d] = s;
    }
    if (blockIdx.x == 0 && blockIdx.y == 0 && tid < CC) {
        float s = b1[tid];
        for (int e = 0; e < CC; e++) s = fmaf(bp2[e], W1s[e*CC + tid], s);
        g_c0[tid] = s;
    }
}

// ---------------------------------------------------------------------------
// prep2: build Mt (=M^T) fp16, plain n-major (row=d, 64 packed k-pairs)
// ---------------------------------------------------------------------------
__global__ void prep2() {
    int i = blockIdx.x * 256 + threadIdx.x;      // 0..8191
    int d = i >> 6, pc = i & 63, c = pc * 2;
    g_Bf[d*64 + pc] = pack_f16(g_M[c*CC + d], g_M[(c+1)*CC + d]);
}

// ---------------------------------------------------------------------------
// proj: v = x@Wv, qW1 = x@Wq1, kW1 = x@Wk1  (fp32 SIMT)
// ---------------------------------------------------------------------------
__global__ __launch_bounds__(256, 2)
void proj_kernel(const float* __restrict__ x, const float* __restrict__ Wv) {
    extern __shared__ float sm[];
    float* Wsh = sm;
    float* Xsh = sm + CC*CC;
    int which = blockIdx.y;
    const float* W = (which == 0) ? Wv  : ((which == 1) ? g_Wq1 : g_Wk1);
    float*       O = (which == 0) ? g_v : ((which == 1) ? g_qW1 : g_kW1);
    int row0 = blockIdx.x * 64;
    int tid = threadIdx.x;
    for (int i = tid; i < CC*CC/4; i += 256) ((float4*)Wsh)[i] = ((const float4*)W)[i];
    for (int i = tid; i < 64*CC; i += 256) {
        int r = i >> 7, c = i & 127;
        Xsh[r*US + c] = x[(row0 + r)*CC + c];
    }
    __syncthreads();
    int tx = tid & 15, ty = tid >> 4;
    float acc[4][8];
    #pragma unroll
    for (int i = 0; i < 4; i++)
        #pragma unroll
        for (int j = 0; j < 8; j++) acc[i][j] = 0.f;
    #pragma unroll 4
    for (int c = 0; c < CC; c++) {
        float4 m0 = *(const float4*)&Wsh[c*CC + (tx << 3)];
        float4 m1 = *(const float4*)&Wsh[c*CC + (tx << 3) + 4];
        float m[8] = {m0.x, m0.y, m0.z, m0.w, m1.x, m1.y, m1.z, m1.w};
        float u[4];
        #pragma unroll
        for (int i = 0; i < 4; i++) u[i] = Xsh[(ty*4 + i)*US + c];
        #pragma unroll
        for (int i = 0; i < 4; i++)
            #pragma unroll
            for (int j = 0; j < 8; j++) acc[i][j] += u[i] * m[j];
    }
    #pragma unroll
    for (int i = 0; i < 4; i++) {
        float4* o4 = (float4*)&O[(row0 + ty*4 + i)*CC + (tx << 3)];
        o4[0] = make_float4(acc[i][0], acc[i][1], acc[i][2], acc[i][3]);
        o4[1] = make_float4(acc[i][4], acc[i][5], acc[i][6], acc[i][7]);
    }
}

// ---------------------------------------------------------------------------
// main: per (n,a) block, 256 threads / 8 warps, FOUR blocks/SM. (R14 struct)
// Bf XOR-swizzled (32KB), Uf padded (17KB, reused as fp16 G buffer after each
// chunk's GEMM). Coalesced row-sweep epilogue with 4-row-batched shuffle
// reductions (ILP). Shuffle softmax. att@v, residual.
// ---------------------------------------------------------------------------
__global__ __launch_bounds__(256, 4)
void main_kernel(const float* __restrict__ x, const float* __restrict__ pos,
                 const float* __restrict__ W2, const float* __restrict__ Wp1,
                 const float* __restrict__ bp1, float* __restrict__ out) {
    extern __shared__ __align__(16) char dyn[];
    __shared__ float kcsh[CC], W2sh[CC], wpa[CC], wpb[CC], bpsh[CC];
    __shared__ float logits[PP], red[PP], wred[16];

    const int blk = blockIdx.x;
    const int n = blk >> 8, a = blk & 255;
    const int tid = threadIdx.x;
    const int lane = tid & 31, w = tid >> 5;

    // dyn layout (bytes): Bf 32768 (swizzled, 256B rows) | Uf/Gs 17408 (pad 68)
    unsigned* Uf = (unsigned*)(dyn + 32768);
    const uint32_t BfA = smem_u32(dyn);
    const uint32_t UfA = BfA + 32768;

    // stage small vectors + B tile (swizzled granules: g' = g ^ (row&7))
    if (tid < CC) {
        kcsh[tid] = g_c0[tid] - g_kW1[(n*PP + a)*CC + tid];
        W2sh[tid] = W2[tid];
        wpa[tid]  = Wp1[tid];
        wpb[tid]  = Wp1[CC + tid];
        bpsh[tid] = bp1[tid];
    }
    for (int i = tid; i < CC*16; i += 256) {
        int r = i >> 4, g = i & 15;
        uint4 v = ((const uint4*)(g_Bf + r*64))[g];
        *(uint4*)(dyn + r*256 + ((g ^ (r & 7)) << 4)) = v;
    }
    __syncthreads();

    // warp roles (GEMM)
    const int ci = w & 3;          // c-quarter: cols [ci*32, +32)
    const int mh = w >> 2;         // m-half within 64-row chunk
    const int n0 = ci * 32;
    const int m0 = mh * 32;

    const int arow = ((lane >> 3) & 1) * 8 + (lane & 7);
    const int acol = (lane >> 4) * 8;
    const int brow = lane & 15;
    const int gb   = lane >> 4;                 // B granule base

    const uint32_t aoffb = (uint32_t)(((m0 + arow) * HS) + acol) * 2u;
    const uint32_t browb = (uint32_t)((n0 + brow) * 256);
    const int      brx   = brow & 7;

    const int jcol = tid & 63;          // U-build column pair (fixed/thread)
    const int c2 = jcol * 2;
    const int rbase = tid >> 6;         // 0..3

    // hoisted per-lane epilogue constants: cols lane*4 .. lane*4+3
    const float kcE0 = kcsh[lane*4],   kcE1 = kcsh[lane*4+1];
    const float kcE2 = kcsh[lane*4+2], kcE3 = kcsh[lane*4+3];
    const float w2E0 = W2sh[lane*4],   w2E1 = W2sh[lane*4+1];
    const float w2E2 = W2sh[lane*4+2], w2E3 = W2sh[lane*4+3];

    const float2* posrow = (const float2*)(pos + (size_t)((n*PP + a)*PP) * 2);
    const float* qbase = g_qW1 + (size_t)(n*PP)*CC;

    #pragma unroll 1
    for (int chunk = 0; chunk < 4; chunk++) {
        // build U chunk = relu(pos@Wp1+bp1) -> fp16 (pos straight from L1/L2)
        #pragma unroll
        for (int k = 0; k < 16; k++) {
            int r = rbase + k*4;
            float2 p = __ldg(posrow + chunk*64 + r);
            float u0 = fmaxf(fmaf(p.x, wpa[c2],   fmaf(p.y, wpb[c2],   bpsh[c2]  )), 0.f);
            float u1 = fmaxf(fmaf(p.x, wpa[c2+1], fmaf(p.y, wpb[c2+1], bpsh[c2+1])), 0.f);
            Uf[r*68 + jcol] = pack_f16(u0, u1);
        }
        __syncthreads();

        // warp GEMM: m32 x n32 x k128, single-term fp16
        float acc[2][4][4];
        #pragma unroll
        for (int ms = 0; ms < 2; ms++)
            #pragma unroll
            for (int nt = 0; nt < 4; nt++)
                #pragma unroll
                for (int e = 0; e < 4; e++) acc[ms][nt][e] = 0.f;

        #pragma unroll
        for (int kt = 0; kt < 8; kt++) {
            const uint32_t ka = (uint32_t)(kt * 16) * 2u;
            const uint32_t sw = (uint32_t)(((gb + 2*kt) ^ brx) << 4);
            uint32_t b0[4], b1[4];
            ldsm_x4(b0, BfA + browb + sw);
            ldsm_x4(b1, BfA + browb + 4096u + sw);
            #pragma unroll
            for (int ms = 0; ms < 2; ms++) {
                const uint32_t ao = aoffb + (uint32_t)(ms * 16 * HS) * 2u + ka;
                uint32_t ah[4];
                ldsm_x4(ah, UfA + ao);
                #pragma unroll
                for (int sub = 0; sub < 2; sub++) {
                    mma16816h(acc[ms][sub],   ah, b0[sub], b0[2+sub]);
                    mma16816h(acc[ms][2+sub], ah, b1[sub], b1[2+sub]);
                }
            }
        }
        __syncthreads();   // all warps done reading Uf (A) before overwrite

        // dump G (fp16 pairs) into Uf-as-Gs; conflict-free STS
        #pragma unroll
        for (int ms = 0; ms < 2; ms++)
            #pragma unroll
            for (int rh = 0; rh < 2; rh++) {
                int row = m0 + ms*16 + rh*8 + (lane >> 2);
                #pragma unroll
                for (int nt = 0; nt < 4; nt++) {
                    unsigned gp = pack_f16(acc[ms][nt][rh*2 + 0], acc[ms][nt][rh*2 + 1]);
                    Uf[row*68 + ci*16 + nt*4 + (lane & 3)] = gp;
                }
            }
        __syncthreads();

        // coalesced epilogue: warp w sweeps rows w*8..w*8+7 in two 4-row
        // batches; shuffle chains interleaved for ILP
        #pragma unroll
        for (int half = 0; half < 2; half++) {
            float rp[4];
            #pragma unroll
            for (int rr = 0; rr < 4; rr++) {
                int r = w*8 + half*4 + rr;
                int bg = chunk*64 + r;
                uint2 g2 = *(const uint2*)&Uf[r*68 + lane*2];
                float4 q4 = __ldg((const float4*)(qbase + (size_t)bg*CC + lane*4));
                float2 ga = __half22float2(*(const __half2*)&g2.x);
                float2 gbv = __half22float2(*(const __half2*)&g2.y);
                float t = fmaxf(ga.x  + q4.x + kcE0, 0.f) * w2E0;
                t = fmaf(fmaxf(ga.y  + q4.y + kcE1, 0.f), w2E1, t);
                t = fmaf(fmaxf(gbv.x + q4.z + kcE2, 0.f), w2E2, t);
                t = fmaf(fmaxf(gbv.y + q4.w + kcE3, 0.f), w2E3, t);
                rp[rr] = t;
            }
            #pragma unroll
            for (int o = 16; o > 0; o >>= 1) {
                #pragma unroll
                for (int rr = 0; rr < 4; rr++)
                    rp[rr] += __shfl_xor_sync(0xffffffffu, rp[rr], o);
            }
            if (lane == 0) {
                int bg0 = chunk*64 + w*8 + half*4;
                logits[bg0    ] = rp[0];
                logits[bg0 + 1] = rp[1];
                logits[bg0 + 2] = rp[2];
                logits[bg0 + 3] = rp[3];
            }
        }
        __syncthreads();   // Gs consumed before next chunk's U build
    }

    // softmax over b (256 entries) — shuffle-based
    float lv = logits[tid];
    {
        float m = lv;
        #pragma unroll
        for (int o = 16; o > 0; o >>= 1) m = fmaxf(m, __shfl_xor_sync(0xffffffffu, m, o));
        if (lane == 0) wred[w] = m;
    }
    __syncthreads();
    float mx = wred[0];
    #pragma unroll
    for (int i = 1; i < 8; i++) mx = fmaxf(mx, wred[i]);
    float ev = expf(lv - mx);
    {
        float s = ev;
        #pragma unroll
        for (int o = 16; o > 0; o >>= 1) s += __shfl_xor_sync(0xffffffffu, s, o);
        if (lane == 0) wred[8 + w] = s;
    }
    __syncthreads();
    float sum = (wred[8] + wred[9]) + (wred[10] + wred[11])
              + (wred[12] + wred[13]) + (wred[14] + wred[15]);
    logits[tid] = ev * (1.0f / sum);
    __syncthreads();

    // out[n,a,:] = x[n,a,:] + att @ v[n]   (2-way split of the b-sum)
    {
        int d = tid & 127, h = tid >> 7;       // h in 0..1
        const float* vb = &g_v[(size_t)(n*PP + h*128)*CC + d];
        float s0 = 0.f, s1 = 0.f;
        #pragma unroll 4
        for (int b = 0; b < 128; b += 2) {
            s0 = fmaf(logits[h*128 + b    ], vb[(size_t)b*CC],     s0);
            s1 = fmaf(logits[h*128 + b + 1], vb[(size_t)(b+1)*CC], s1);
        }
        red[tid] = s0 + s1;
    }
    __syncthreads();
    if (tid < CC) {
        size_t o = (size_t)(n*PP + a)*CC + tid;
        out[o] = x[o] + red[tid] + red[tid + 128];
    }
}

// ---------------------------------------------------------------------------
extern "C" void kernel_launch(void* const* d_in, const int* in_sizes, int n_in,
                              void* d_out, int out_size) {
    const float* x   = (const float*)d_in[0];
    const float* pos = (const float*)d_in[1];
    const float* Wq  = (const float*)d_in[2];
    const float* Wk  = (const float*)d_in[3];
    const float* Wv  = (const float*)d_in[4];
    const float* W1  = (const float*)d_in[5];
    const float* b1  = (const float*)d_in[6];
    const float* W2  = (const float*)d_in[7];
    // d_in[8] = b2: cancelled by softmax
    const float* Wp1 = (const float*)d_in[9];
    const float* bp1 = (const float*)d_in[10];
    const float* Wp2 = (const float*)d_in[11];
    const float* bp2 = (const float*)d_in[12];
    float* out = (float*)d_out;

    const int smem_prep = (CC*CC + 16*CC) * 4;   // 73728
    const int smem_proj = (CC*CC + 64*US) * 4;   // 99328
    const int smem_main = 50176;                 // Bf swizzled 32K + Uf/Gs 17K
    cudaFuncSetAttribute(prep1,       cudaFuncAttributeMaxDynamicSharedMemorySize, smem_prep);
    cudaFuncSetAttribute(proj_kernel, cudaFuncAttributeMaxDynamicSharedMemorySize, smem_proj);
    cudaFuncSetAttribute(main_kernel, cudaFuncAttributeMaxDynamicSharedMemorySize, smem_main);

    prep1<<<dim3(8, 3), 256, smem_prep>>>(Wq, Wk, Wp2, W1, b1, bp2);
    prep2<<<32, 256>>>();
    proj_kernel<<<dim3(NB*PP/64, 3), 256, smem_proj>>>(x, Wv);
    main_kernel<<<NB*PP, 256, smem_main>>>(x, pos, W2, Wp1, bp1, out);
}